// round 1
// baseline (speedup 1.0000x reference)
#include <cuda_runtime.h>

#define B_TOT 16384
#define F_    64
#define NB_   64
#define H1_   128
#define H2_   128
#define BT_   64
#define NTHREADS 256

typedef unsigned long long ull;

// ---------- packed f32x2 helpers (sm_100+ PTX) ----------
__device__ __forceinline__ ull pk2(float lo, float hi) {
    ull r;
    asm("mov.b64 %0, {%1, %2};" : "=l"(r) : "f"(lo), "f"(hi));
    return r;
}
__device__ __forceinline__ void fma2(ull& d, ull a, ull b) {
    asm("fma.rn.f32x2 %0, %1, %2, %0;" : "+l"(d) : "l"(a), "l"(b));
}
__device__ __forceinline__ float2 upk2(ull v) {
    float lo, hi;
    asm("mov.b64 {%0, %1}, %2;" : "=f"(lo), "=f"(hi) : "l"(v));
    return make_float2(lo, hi);
}

__device__ __forceinline__ float warp_sum(float v) {
#pragma unroll
    for (int o = 16; o; o >>= 1) v += __shfl_xor_sync(0xffffffffu, v, o);
    return v;
}
__device__ __forceinline__ float clampf(float v, float lo, float hi) {
    return fminf(fmaxf(v, lo), hi);
}
__device__ __forceinline__ float gelu_f(float x) {
    return 0.5f * x * (1.0f + erff(x * 0.7071067811865475f));
}
__device__ __forceinline__ float softplus_f(float x) {
    return (x > 15.0f) ? x : log1pf(expf(x));
}

// ---------- register-tiled GEMM: out[64][128] += act[64][K] * Wsmem[K][128] ----------
// warp wid owns rows r0..r0+7; lane owns cols c0..c0+3 (2 packed pairs).
// Weights: LDS.128 coalesced. Activations: broadcast LDS.64 (2 K-steps at once).
template<int KDIM>
__device__ __forceinline__ void gemm_acc(ull (&acc)[8][2],
                                         const float* __restrict__ act, int actStride,
                                         const float* __restrict__ ws, int r0, int c0)
{
#pragma unroll 4
    for (int n = 0; n < KDIM; n += 2) {
        float4 wA = *(const float4*)&ws[n * 128 + c0];
        float4 wB = *(const float4*)&ws[(n + 1) * 128 + c0];
        ull wA0 = pk2(wA.x, wA.y), wA1 = pk2(wA.z, wA.w);
        ull wB0 = pk2(wB.x, wB.y), wB1 = pk2(wB.z, wB.w);
#pragma unroll
        for (int r = 0; r < 8; ++r) {
            float2 a = *(const float2*)&act[(r0 + r) * actStride + n];
            ull aA = pk2(a.x, a.x);
            ull aB = pk2(a.y, a.y);
            fma2(acc[r][0], aA, wA0);
            fma2(acc[r][1], aA, wA1);
            fma2(acc[r][0], aB, wB0);
            fma2(acc[r][1], aB, wB1);
        }
    }
}

// LN over 128 cols (warp-local: 32 lanes x 4 cols) then exact GELU
__device__ __forceinline__ void ln_gelu4(float& v0, float& v1, float& v2, float& v3,
                                         float4 gv, float4 ev)
{
    float S = warp_sum(v0 + v1 + v2 + v3);
    float mu = S * (1.0f / 128.0f);
    float d0 = v0 - mu, d1 = v1 - mu, d2 = v2 - mu, d3 = v3 - mu;
    float Q = warp_sum(d0 * d0 + d1 * d1 + d2 * d2 + d3 * d3);
    float rstd = rsqrtf(Q * (1.0f / 128.0f) + 1e-5f);
    v0 = gelu_f(d0 * rstd * gv.x + ev.x);
    v1 = gelu_f(d1 * rstd * gv.y + ev.y);
    v2 = gelu_f(d2 * rstd * gv.z + ev.z);
    v3 = gelu_f(d3 * rstd * gv.w + ev.w);
}

__global__ void __launch_bounds__(NTHREADS, 2)
nam_fused_kernel(const float* __restrict__ x,
                 const float* __restrict__ centers,
                 const float* __restrict__ logw,
                 const float* __restrict__ W1,  const float* __restrict__ b1,
                 const float* __restrict__ g1,  const float* __restrict__ be1,
                 const float* __restrict__ W2,  const float* __restrict__ b2,
                 const float* __restrict__ g2,  const float* __restrict__ be2,
                 const float* __restrict__ Wr,  const float* __restrict__ br,
                 const float* __restrict__ att, const float* __restrict__ bias,
                 const float* __restrict__ Wpi, const float* __restrict__ bpi,
                 const float* __restrict__ Wa,  const float* __restrict__ ba,
                 const float* __restrict__ Wb,  const float* __restrict__ bb,
                 float* __restrict__ out)
{
    extern __shared__ float smem[];
    float* rbf_s = smem;                         // 64*64   = 4096 floats
    float* a1_s  = smem + 4096;                  // 64*128  = 8192 floats
    float* ws    = smem + 4096 + 8192;           // 8192 floats (32KB stage)
    float* wfs   = smem + 4096 + 8192 + 8192;    // 64 floats

    const int tid  = threadIdx.x;
    const int wid  = tid >> 5;
    const int lane = tid & 31;
    const int b0   = blockIdx.x * BT_;
    const int r0   = wid * 8;
    const int c0   = lane * 4;

    // softmax(att) once per CTA
    if (tid == 0) {
        float mx = -3.4e38f;
        for (int i = 0; i < F_; ++i) mx = fmaxf(mx, att[i]);
        float s = 0.0f;
        for (int i = 0; i < F_; ++i) { float e = expf(att[i] - mx); wfs[i] = e; s += e; }
        float inv = 1.0f / s;
        for (int i = 0; i < F_; ++i) wfs[i] *= inv;
    }

    float agg[8][4];
#pragma unroll
    for (int r = 0; r < 8; ++r)
#pragma unroll
        for (int j = 0; j < 4; ++j) agg[r][j] = 0.0f;

    for (int f = 0; f < F_; ++f) {
        __syncthreads();  // prev iter done with rbf_s + ws

        // ---- RBF expansion for this feature: rbf_s[r][n] ----
#pragma unroll
        for (int k = 0; k < (BT_ * NB_) / NTHREADS; ++k) {
            int idx = tid + k * NTHREADS;
            int r = idx >> 6, n = idx & 63;
            float xv = x[(b0 + r) * F_ + f];
            xv = clampf(xv, -10.0f, 10.0f);
            float c  = centers[f * NB_ + n];
            float lw = clampf(logw[f * NB_ + n], -5.0f, 5.0f);
            float wd = __expf(lw) + 0.1f;
            float d  = __fdividef(xv - c, wd);
            d = clampf(d, -10.0f, 10.0f);
            rbf_s[idx] = __expf(-0.5f * d * d);
        }
        // ---- stage W1[f] (32KB) ----
        {
            const float4* g = (const float4*)(W1 + (size_t)f * NB_ * H1_);
            float4* s4 = (float4*)ws;
#pragma unroll
            for (int k = 0; k < 8; ++k) s4[tid + k * NTHREADS] = g[tid + k * NTHREADS];
        }
        __syncthreads();

        // ---- GEMM1: rbf @ W1 ----
        ull acc[8][2];
#pragma unroll
        for (int r = 0; r < 8; ++r) { acc[r][0] = 0ull; acc[r][1] = 0ull; }
        gemm_acc<NB_>(acc, rbf_s, NB_, ws, r0, c0);

        // epilogue 1: +b1, LN(g1,be1), GELU -> a1_s (own rows only, no sync needed)
        {
            float4 bv = *(const float4*)&b1[f * H1_ + c0];
            float4 gv = *(const float4*)&g1[f * H1_ + c0];
            float4 ev = *(const float4*)&be1[f * H1_ + c0];
#pragma unroll
            for (int r = 0; r < 8; ++r) {
                float2 p0 = upk2(acc[r][0]), p1 = upk2(acc[r][1]);
                float v0 = p0.x + bv.x, v1 = p0.y + bv.y;
                float v2 = p1.x + bv.z, v3 = p1.y + bv.w;
                ln_gelu4(v0, v1, v2, v3, gv, ev);
                *(float4*)&a1_s[(r0 + r) * H1_ + c0] = make_float4(v0, v1, v2, v3);
            }
        }

        // ---- GEMM2: a1 @ W2, staged in two 32KB halves ----
        ull acc2[8][2];
#pragma unroll
        for (int r = 0; r < 8; ++r) { acc2[r][0] = 0ull; acc2[r][1] = 0ull; }
        for (int half = 0; half < 2; ++half) {
            __syncthreads();  // all warps done reading ws
            const float4* g = (const float4*)(W2 + (size_t)f * H1_ * H2_ + half * 8192);
            float4* s4 = (float4*)ws;
#pragma unroll
            for (int k = 0; k < 8; ++k) s4[tid + k * NTHREADS] = g[tid + k * NTHREADS];
            __syncthreads();
            gemm_acc<64>(acc2, a1_s + half * 64, H1_, ws, r0, c0);
        }

        // epilogue 2: +b2, LN(g2,be2), GELU; agg += w_f * h
        const float wf = wfs[f];
        {
            float4 bv = *(const float4*)&b2[f * H2_ + c0];
            float4 gv = *(const float4*)&g2[f * H2_ + c0];
            float4 ev = *(const float4*)&be2[f * H2_ + c0];
#pragma unroll
            for (int r = 0; r < 8; ++r) {
                float2 p0 = upk2(acc2[r][0]), p1 = upk2(acc2[r][1]);
                float v0 = p0.x + bv.x, v1 = p0.y + bv.y;
                float v2 = p1.x + bv.z, v3 = p1.y + bv.w;
                ln_gelu4(v0, v1, v2, v3, gv, ev);
                agg[r][0] += wf * v0;
                agg[r][1] += wf * v1;
                agg[r][2] += wf * v2;
                agg[r][3] += wf * v3;
            }
        }

        // ---- residual GEMM: rbf @ Wr ----
        __syncthreads();
        {
            const float4* g = (const float4*)(Wr + (size_t)f * NB_ * H2_);
            float4* s4 = (float4*)ws;
#pragma unroll
            for (int k = 0; k < 8; ++k) s4[tid + k * NTHREADS] = g[tid + k * NTHREADS];
        }
        __syncthreads();
        ull accr[8][2];
#pragma unroll
        for (int r = 0; r < 8; ++r) { accr[r][0] = 0ull; accr[r][1] = 0ull; }
        gemm_acc<NB_>(accr, rbf_s, NB_, ws, r0, c0);
        {
            float4 bv = *(const float4*)&br[f * H2_ + c0];
            const float wfr = 0.1f * wf;
#pragma unroll
            for (int r = 0; r < 8; ++r) {
                float2 p0 = upk2(accr[r][0]), p1 = upk2(accr[r][1]);
                agg[r][0] += wfr * (p0.x + bv.x);
                agg[r][1] += wfr * (p0.y + bv.y);
                agg[r][2] += wfr * (p1.x + bv.z);
                agg[r][3] += wfr * (p1.y + bv.w);
            }
        }
    }

    // ---- mixture-beta head ----
    float4 biasv = *(const float4*)&bias[c0];
    const float bias_l[4] = { biasv.x, biasv.y, biasv.z, biasv.w };
    float wpi[4][3], wa[4][3], wb[4][3];
#pragma unroll
    for (int j = 0; j < 4; ++j) {
        int h = c0 + j;
#pragma unroll
        for (int k = 0; k < 3; ++k) {
            wpi[j][k] = Wpi[h * 3 + k];
            wa[j][k]  = Wa[h * 3 + k];
            wb[j][k]  = Wb[h * 3 + k];
        }
    }
    const float bpi0 = bpi[0], bpi1 = bpi[1], bpi2 = bpi[2];
    const float ba0 = ba[0], ba1 = ba[1], ba2 = ba[2];
    const float bb0 = bb[0], bb1 = bb[1], bb2 = bb[2];

#pragma unroll
    for (int r = 0; r < 8; ++r) {
        float zp[3] = {0.f, 0.f, 0.f}, za[3] = {0.f, 0.f, 0.f}, zb[3] = {0.f, 0.f, 0.f};
#pragma unroll
        for (int j = 0; j < 4; ++j) {
            float av = agg[r][j] + bias_l[j];
#pragma unroll
            for (int k = 0; k < 3; ++k) {
                zp[k] = fmaf(av, wpi[j][k], zp[k]);
                za[k] = fmaf(av, wa[j][k],  za[k]);
                zb[k] = fmaf(av, wb[j][k],  zb[k]);
            }
        }
#pragma unroll
        for (int k = 0; k < 3; ++k) {
            zp[k] = warp_sum(zp[k]);
            za[k] = warp_sum(za[k]);
            zb[k] = warp_sum(zb[k]);
        }
        float p0 = zp[0] + bpi0, p1 = zp[1] + bpi1, p2 = zp[2] + bpi2;
        float m  = fmaxf(p0, fmaxf(p1, p2));
        float e0 = expf(p0 - m), e1 = expf(p1 - m), e2 = expf(p2 - m);

        float al0 = clampf(softplus_f(za[0] + ba0) + 1.01f, 1.01f, 100.0f);
        float al1 = clampf(softplus_f(za[1] + ba1) + 1.01f, 1.01f, 100.0f);
        float al2 = clampf(softplus_f(za[2] + ba2) + 1.01f, 1.01f, 100.0f);
        float bt0 = clampf(softplus_f(zb[0] + bb0) + 1.01f, 1.01f, 100.0f);
        float bt1 = clampf(softplus_f(zb[1] + bb1) + 1.01f, 1.01f, 100.0f);
        float bt2 = clampf(softplus_f(zb[2] + bb2) + 1.01f, 1.01f, 100.0f);

        float pred = e0 * al0 / (al0 + bt0)
                   + e1 * al1 / (al1 + bt1)
                   + e2 * al2 / (al2 + bt2);
        pred /= (e0 + e1 + e2);
        pred = clampf(pred, 0.001f, 0.999f);
        if (lane == 0) out[b0 + r0 + r] = pred;
    }
}

extern "C" void kernel_launch(void* const* d_in, const int* in_sizes, int n_in,
                              void* d_out, int out_size)
{
    const float* x       = (const float*)d_in[0];
    const float* centers = (const float*)d_in[1];
    const float* logw    = (const float*)d_in[2];
    const float* W1      = (const float*)d_in[3];
    const float* b1      = (const float*)d_in[4];
    const float* g1      = (const float*)d_in[5];
    const float* be1     = (const float*)d_in[6];
    const float* W2      = (const float*)d_in[7];
    const float* b2      = (const float*)d_in[8];
    const float* g2      = (const float*)d_in[9];
    const float* be2     = (const float*)d_in[10];
    const float* Wr      = (const float*)d_in[11];
    const float* br      = (const float*)d_in[12];
    const float* att     = (const float*)d_in[13];
    const float* bias    = (const float*)d_in[14];
    const float* Wpi     = (const float*)d_in[15];
    const float* bpi     = (const float*)d_in[16];
    const float* Wa      = (const float*)d_in[17];
    const float* ba      = (const float*)d_in[18];
    const float* Wb      = (const float*)d_in[19];
    const float* bb      = (const float*)d_in[20];
    float* out = (float*)d_out;

    const int smem_bytes = (4096 + 8192 + 8192 + 64) * 4;  // 82176 B
    cudaFuncSetAttribute(nam_fused_kernel,
                         cudaFuncAttributeMaxDynamicSharedMemorySize, smem_bytes);
    nam_fused_kernel<<<B_TOT / BT_, NTHREADS, smem_bytes>>>(
        x, centers, logw, W1, b1, g1, be1, W2, b2, g2, be2,
        Wr, br, att, bias, Wpi, bpi, Wa, ba, Wb, bb, out);
}

// round 2
// speedup vs baseline: 1.9213x; 1.9213x over previous
#include <cuda_runtime.h>
#include <cstdint>

#define B_TOT 16384
#define F_    64
#define BT_   64
#define NTHREADS 256

// SMEM float offsets
#define RBF_OFF 0            // 64 x 68   = 4352
#define A1_OFF  4352         // 64 x 132  = 8448
#define WS_OFF  12800        // 64 x 136  = 8704
#define PB_OFF  21504        // 7 x 128   = 896
#define WFS_OFF 22400        // 64
#define LN_OFF  22464        // 2*64*2 = 256 (reused as head buf 2*64*9 = 1152)
#define SMEM_FLOATS (22464 + 1152)

#define SA_RBF 68
#define SA_A1  132
#define SW     136

__device__ __forceinline__ uint32_t f2tf32(float f) {
    uint32_t u;
    asm("cvt.rna.tf32.f32 %0, %1;" : "=r"(u) : "f"(f));
    return u;
}
__device__ __forceinline__ void mma8(float (&d)[4],
                                     uint32_t a0, uint32_t a1, uint32_t a2, uint32_t a3,
                                     uint32_t b0, uint32_t b1) {
    asm("mma.sync.aligned.m16n8k8.row.col.f32.tf32.tf32.f32 "
        "{%0,%1,%2,%3},{%4,%5,%6,%7},{%8,%9},{%0,%1,%2,%3};"
        : "+f"(d[0]), "+f"(d[1]), "+f"(d[2]), "+f"(d[3])
        : "r"(a0), "r"(a1), "r"(a2), "r"(a3), "r"(b0), "r"(b1));
}
__device__ __forceinline__ float clampf(float v, float lo, float hi) {
    return fminf(fmaxf(v, lo), hi);
}
__device__ __forceinline__ float gelu_f(float x) {
    return 0.5f * x * (1.0f + erff(x * 0.7071067811865475f));
}
__device__ __forceinline__ float softplus_f(float x) {
    return (x > 15.0f) ? x : log1pf(expf(x));
}
__device__ __forceinline__ float quad_sum(float v) {
    v += __shfl_xor_sync(0xffffffffu, v, 1);
    v += __shfl_xor_sync(0xffffffffu, v, 2);
    return v;
}

// KSTEPS k-chunks of 8. A: padded row-major [rows][strideA], tf32 bits.
// ws: padded [64][SW] tf32 bits. acc[j] covers n-tile j (cols nbase + j*8).
template<int KSTEPS>
__device__ __forceinline__ void gemm_steps(float (&acc)[8][4],
                                           const float* __restrict__ A, int sA, int rA0,
                                           const float* __restrict__ ws, int nbg, int t,
                                           int kA0)
{
#pragma unroll
    for (int ks = 0; ks < KSTEPS; ++ks) {
        const int k = ks * 8;
        const float* ar0 = A + rA0 * sA + kA0 + k + t;
        const float* ar1 = ar0 + 8 * sA;
        uint32_t a0 = __float_as_uint(ar0[0]);
        uint32_t a2 = __float_as_uint(ar0[4]);
        uint32_t a1 = __float_as_uint(ar1[0]);
        uint32_t a3 = __float_as_uint(ar1[4]);
        const float* wp0 = ws + (k + t) * SW + nbg;
        const float* wp1 = wp0 + 4 * SW;
#pragma unroll
        for (int j = 0; j < 8; ++j) {
            uint32_t b0 = __float_as_uint(wp0[j * 8]);
            uint32_t b1 = __float_as_uint(wp1[j * 8]);
            mma8(acc[j], a0, a1, a2, a3, b0, b1);
        }
    }
}

// stage 64x128 weight block (row-major, 2048 float4) into ws with tf32 cvt
__device__ __forceinline__ void stage_w(float* __restrict__ ws,
                                        const float4* __restrict__ g, int tid)
{
#pragma unroll
    for (int kk = 0; kk < 8; ++kk) {
        int idx = tid + kk * NTHREADS;
        int k = idx >> 5, n4 = idx & 31;
        float4 v = g[idx];
        uint4 u = make_uint4(f2tf32(v.x), f2tf32(v.y), f2tf32(v.z), f2tf32(v.w));
        *(uint4*)&ws[k * SW + n4 * 4] = u;
    }
}

__global__ void __launch_bounds__(NTHREADS, 2)
nam_mma_kernel(const float* __restrict__ x,
               const float* __restrict__ centers,
               const float* __restrict__ logw,
               const float* __restrict__ W1,  const float* __restrict__ b1,
               const float* __restrict__ g1,  const float* __restrict__ be1,
               const float* __restrict__ W2,  const float* __restrict__ b2,
               const float* __restrict__ g2,  const float* __restrict__ be2,
               const float* __restrict__ Wr,  const float* __restrict__ br,
               const float* __restrict__ att, const float* __restrict__ bias,
               const float* __restrict__ Wpi, const float* __restrict__ bpi,
               const float* __restrict__ Wa,  const float* __restrict__ ba,
               const float* __restrict__ Wb,  const float* __restrict__ bb,
               float* __restrict__ out)
{
    extern __shared__ float sm[];
    float* rbf = sm + RBF_OFF;
    float* a1s = sm + A1_OFF;
    float* ws  = sm + WS_OFF;
    float* pb  = sm + PB_OFF;
    float* wfs = sm + WFS_OFF;
    float* lnb = sm + LN_OFF;
    float* hb  = sm + LN_OFF;   // reused after feature loop

    const int tid  = threadIdx.x;
    const int wid  = tid >> 5;
    const int lane = tid & 31;
    const int g    = lane >> 2;    // 0..7
    const int t    = lane & 3;     // 0..3
    const int wr   = wid >> 1;     // row group 0..3
    const int wc   = wid & 1;      // col group 0..1
    const int rA0  = wr * 16 + g;  // thread row 0 (row 1 = +8)
    const int nbg  = wc * 64 + g;  // B-fragment col base
    const int b0blk = blockIdx.x * BT_;

    if (tid == 0) {
        float mx = -3.4e38f;
        for (int i = 0; i < F_; ++i) mx = fmaxf(mx, att[i]);
        float s = 0.0f;
        for (int i = 0; i < F_; ++i) { float e = expf(att[i] - mx); wfs[i] = e; s += e; }
        float inv = 1.0f / s;
        for (int i = 0; i < F_; ++i) wfs[i] *= inv;
    }

    float agg[2][16];
#pragma unroll
    for (int r = 0; r < 2; ++r)
#pragma unroll
        for (int j = 0; j < 16; ++j) agg[r][j] = 0.0f;

    for (int f = 0; f < F_; ++f) {
        __syncthreads();  // S0: rbf/ws/pb free

        // ---- RBF expansion (tf32-rounded into padded smem) ----
#pragma unroll
        for (int kk = 0; kk < 16; ++kk) {
            int idx = tid + kk * NTHREADS;
            int r = idx >> 6, n = idx & 63;
            float xv = clampf(x[(b0blk + r) * F_ + f], -10.0f, 10.0f);
            float c  = centers[f * 64 + n];
            float lw = clampf(logw[f * 64 + n], -5.0f, 5.0f);
            float wd = __expf(lw) + 0.1f;
            float d  = clampf(__fdividef(xv - c, wd), -10.0f, 10.0f);
            rbf[r * SA_RBF + n] = __uint_as_float(f2tf32(__expf(-0.5f * d * d)));
        }
        // ---- stage W1 + per-feature params ----
        stage_w(ws, (const float4*)(W1 + (size_t)f * 8192), tid);
        if (tid < 128) {
            pb[tid]       = b1 [f * 128 + tid];
            pb[128 + tid] = g1 [f * 128 + tid];
            pb[256 + tid] = be1[f * 128 + tid];
            pb[384 + tid] = b2 [f * 128 + tid];
        } else {
            int s = tid - 128;
            pb[512 + s] = g2 [f * 128 + s];
            pb[640 + s] = be2[f * 128 + s];
            pb[768 + s] = br [f * 128 + s];
        }
        __syncthreads();  // S1

        // ---- GEMM1: rbf[64x64] @ W1[64x128] ----
        float acc[8][4];
#pragma unroll
        for (int j = 0; j < 8; ++j) { acc[j][0] = acc[j][1] = acc[j][2] = acc[j][3] = 0.f; }
        gemm_steps<8>(acc, rbf, SA_RBF, rA0, ws, nbg, t, 0);

        // partial LN stats (with +b1)
        {
            float s0 = 0.f, q0 = 0.f, s1 = 0.f, q1 = 0.f;
#pragma unroll
            for (int j = 0; j < 8; ++j) {
                int col = wc * 64 + j * 8 + t * 2;
                float2 bv = *(const float2*)&pb[col];
                float v0 = acc[j][0] + bv.x, v1 = acc[j][1] + bv.y;
                float v2 = acc[j][2] + bv.x, v3 = acc[j][3] + bv.y;
                s0 += v0 + v1; q0 += v0 * v0 + v1 * v1;
                s1 += v2 + v3; q1 += v2 * v2 + v3 * v3;
            }
            s0 = quad_sum(s0); q0 = quad_sum(q0);
            s1 = quad_sum(s1); q1 = quad_sum(q1);
            if (t == 0) {
                *(float2*)&lnb[(wc * 64 + rA0) * 2]     = make_float2(s0, q0);
                *(float2*)&lnb[(wc * 64 + rA0 + 8) * 2] = make_float2(s1, q1);
            }
        }
        __syncthreads();  // S2

        // finalize epilogue 1 -> a1s ; stage W2 half0
        {
            float2 pA0 = *(const float2*)&lnb[rA0 * 2];
            float2 pB0 = *(const float2*)&lnb[(64 + rA0) * 2];
            float2 pA1 = *(const float2*)&lnb[(rA0 + 8) * 2];
            float2 pB1 = *(const float2*)&lnb[(64 + rA0 + 8) * 2];
            float mu0 = (pA0.x + pB0.x) * (1.f / 128.f);
            float va0 = (pA0.y + pB0.y) * (1.f / 128.f) - mu0 * mu0;
            float rs0 = rsqrtf(va0 + 1e-5f);
            float mu1 = (pA1.x + pB1.x) * (1.f / 128.f);
            float va1 = (pA1.y + pB1.y) * (1.f / 128.f) - mu1 * mu1;
            float rs1 = rsqrtf(va1 + 1e-5f);
#pragma unroll
            for (int j = 0; j < 8; ++j) {
                int col = wc * 64 + j * 8 + t * 2;
                float2 bv = *(const float2*)&pb[col];
                float2 gv = *(const float2*)&pb[128 + col];
                float2 ev = *(const float2*)&pb[256 + col];
                float v0 = gelu_f((acc[j][0] + bv.x - mu0) * rs0 * gv.x + ev.x);
                float v1 = gelu_f((acc[j][1] + bv.y - mu0) * rs0 * gv.y + ev.y);
                float v2 = gelu_f((acc[j][2] + bv.x - mu1) * rs1 * gv.x + ev.x);
                float v3 = gelu_f((acc[j][3] + bv.y - mu1) * rs1 * gv.y + ev.y);
                *(float2*)&a1s[rA0 * SA_A1 + col] =
                    make_float2(__uint_as_float(f2tf32(v0)), __uint_as_float(f2tf32(v1)));
                *(float2*)&a1s[(rA0 + 8) * SA_A1 + col] =
                    make_float2(__uint_as_float(f2tf32(v2)), __uint_as_float(f2tf32(v3)));
            }
        }
        stage_w(ws, (const float4*)(W2 + (size_t)f * 16384), tid);
        __syncthreads();  // S3

        float acc2[8][4];
#pragma unroll
        for (int j = 0; j < 8; ++j) { acc2[j][0] = acc2[j][1] = acc2[j][2] = acc2[j][3] = 0.f; }
        gemm_steps<8>(acc2, a1s, SA_A1, rA0, ws, nbg, t, 0);
        __syncthreads();  // S4
        stage_w(ws, (const float4*)(W2 + (size_t)f * 16384) + 2048, tid);
        __syncthreads();  // S5
        gemm_steps<8>(acc2, a1s, SA_A1, rA0, ws, nbg, t, 64);

        // partial LN stats (with +b2)
        {
            float s0 = 0.f, q0 = 0.f, s1 = 0.f, q1 = 0.f;
#pragma unroll
            for (int j = 0; j < 8; ++j) {
                int col = wc * 64 + j * 8 + t * 2;
                float2 bv = *(const float2*)&pb[384 + col];
                float v0 = acc2[j][0] + bv.x, v1 = acc2[j][1] + bv.y;
                float v2 = acc2[j][2] + bv.x, v3 = acc2[j][3] + bv.y;
                s0 += v0 + v1; q0 += v0 * v0 + v1 * v1;
                s1 += v2 + v3; q1 += v2 * v2 + v3 * v3;
            }
            s0 = quad_sum(s0); q0 = quad_sum(q0);
            s1 = quad_sum(s1); q1 = quad_sum(q1);
            if (t == 0) {
                *(float2*)&lnb[(wc * 64 + rA0) * 2]     = make_float2(s0, q0);
                *(float2*)&lnb[(wc * 64 + rA0 + 8) * 2] = make_float2(s1, q1);
            }
        }
        __syncthreads();  // S6

        const float wf = wfs[f];
        {
            float2 pA0 = *(const float2*)&lnb[rA0 * 2];
            float2 pB0 = *(const float2*)&lnb[(64 + rA0) * 2];
            float2 pA1 = *(const float2*)&lnb[(rA0 + 8) * 2];
            float2 pB1 = *(const float2*)&lnb[(64 + rA0 + 8) * 2];
            float mu0 = (pA0.x + pB0.x) * (1.f / 128.f);
            float va0 = (pA0.y + pB0.y) * (1.f / 128.f) - mu0 * mu0;
            float rs0 = rsqrtf(va0 + 1e-5f);
            float mu1 = (pA1.x + pB1.x) * (1.f / 128.f);
            float va1 = (pA1.y + pB1.y) * (1.f / 128.f) - mu1 * mu1;
            float rs1 = rsqrtf(va1 + 1e-5f);
#pragma unroll
            for (int j = 0; j < 8; ++j) {
                int col = wc * 64 + j * 8 + t * 2;
                float2 bv = *(const float2*)&pb[384 + col];
                float2 gv = *(const float2*)&pb[512 + col];
                float2 ev = *(const float2*)&pb[640 + col];
                float v0 = gelu_f((acc2[j][0] + bv.x - mu0) * rs0 * gv.x + ev.x);
                float v1 = gelu_f((acc2[j][1] + bv.y - mu0) * rs0 * gv.y + ev.y);
                float v2 = gelu_f((acc2[j][2] + bv.x - mu1) * rs1 * gv.x + ev.x);
                float v3 = gelu_f((acc2[j][3] + bv.y - mu1) * rs1 * gv.y + ev.y);
                agg[0][j * 2]     += wf * v0;
                agg[0][j * 2 + 1] += wf * v1;
                agg[1][j * 2]     += wf * v2;
                agg[1][j * 2 + 1] += wf * v3;
            }
        }
        stage_w(ws, (const float4*)(Wr + (size_t)f * 8192), tid);
        __syncthreads();  // S7

        float accr[8][4];
#pragma unroll
        for (int j = 0; j < 8; ++j) { accr[j][0] = accr[j][1] = accr[j][2] = accr[j][3] = 0.f; }
        gemm_steps<8>(accr, rbf, SA_RBF, rA0, ws, nbg, t, 0);
        {
            const float c01 = 0.1f * wf;
#pragma unroll
            for (int j = 0; j < 8; ++j) {
                int col = wc * 64 + j * 8 + t * 2;
                float2 bv = *(const float2*)&pb[768 + col];
                agg[0][j * 2]     += c01 * (accr[j][0] + bv.x);
                agg[0][j * 2 + 1] += c01 * (accr[j][1] + bv.y);
                agg[1][j * 2]     += c01 * (accr[j][2] + bv.x);
                agg[1][j * 2 + 1] += c01 * (accr[j][3] + bv.y);
            }
        }
    }

    // ---- mixture-beta head ----
    float p[2][9];
#pragma unroll
    for (int r = 0; r < 2; ++r)
#pragma unroll
        for (int q = 0; q < 9; ++q) p[r][q] = 0.f;

#pragma unroll
    for (int j = 0; j < 8; ++j) {
#pragma unroll
        for (int cc = 0; cc < 2; ++cc) {
            int c = wc * 64 + j * 8 + t * 2 + cc;
            float bs = __ldg(&bias[c]);
            float av0 = agg[0][j * 2 + cc] + bs;
            float av1 = agg[1][j * 2 + cc] + bs;
#pragma unroll
            for (int q = 0; q < 3; ++q) {
                float wp = __ldg(&Wpi[c * 3 + q]);
                float wa = __ldg(&Wa [c * 3 + q]);
                float wb = __ldg(&Wb [c * 3 + q]);
                p[0][q]     += av0 * wp; p[1][q]     += av1 * wp;
                p[0][3 + q] += av0 * wa; p[1][3 + q] += av1 * wa;
                p[0][6 + q] += av0 * wb; p[1][6 + q] += av1 * wb;
            }
        }
    }
#pragma unroll
    for (int r = 0; r < 2; ++r)
#pragma unroll
        for (int q = 0; q < 9; ++q) p[r][q] = quad_sum(p[r][q]);

    if (t == 0) {
#pragma unroll
        for (int q = 0; q < 9; ++q) {
            hb[(wc * 64 + rA0) * 9 + q]     = p[0][q];
            hb[(wc * 64 + rA0 + 8) * 9 + q] = p[1][q];
        }
    }
    __syncthreads();

    if (wc == 0 && t == 0) {
#pragma unroll
        for (int rr = 0; rr < 2; ++rr) {
            int r = rA0 + rr * 8;
            float z[9];
#pragma unroll
            for (int q = 0; q < 9; ++q) z[q] = hb[r * 9 + q] + hb[(64 + r) * 9 + q];
            float p0 = z[0] + bpi[0], p1 = z[1] + bpi[1], p2 = z[2] + bpi[2];
            float m = fmaxf(p0, fmaxf(p1, p2));
            float e0 = expf(p0 - m), e1 = expf(p1 - m), e2 = expf(p2 - m);
            float al0 = clampf(softplus_f(z[3] + ba[0]) + 1.01f, 1.01f, 100.0f);
            float al1 = clampf(softplus_f(z[4] + ba[1]) + 1.01f, 1.01f, 100.0f);
            float al2 = clampf(softplus_f(z[5] + ba[2]) + 1.01f, 1.01f, 100.0f);
            float bt0 = clampf(softplus_f(z[6] + bb[0]) + 1.01f, 1.01f, 100.0f);
            float bt1 = clampf(softplus_f(z[7] + bb[1]) + 1.01f, 1.01f, 100.0f);
            float bt2 = clampf(softplus_f(z[8] + bb[2]) + 1.01f, 1.01f, 100.0f);
            float pred = e0 * al0 / (al0 + bt0)
                       + e1 * al1 / (al1 + bt1)
                       + e2 * al2 / (al2 + bt2);
            pred /= (e0 + e1 + e2);
            out[b0blk + r] = clampf(pred, 0.001f, 0.999f);
        }
    }
}

extern "C" void kernel_launch(void* const* d_in, const int* in_sizes, int n_in,
                              void* d_out, int out_size)
{
    const float* x       = (const float*)d_in[0];
    const float* centers = (const float*)d_in[1];
    const float* logw    = (const float*)d_in[2];
    const float* W1      = (const float*)d_in[3];
    const float* b1      = (const float*)d_in[4];
    const float* g1      = (const float*)d_in[5];
    const float* be1     = (const float*)d_in[6];
    const float* W2      = (const float*)d_in[7];
    const float* b2      = (const float*)d_in[8];
    const float* g2      = (const float*)d_in[9];
    const float* be2     = (const float*)d_in[10];
    const float* Wr      = (const float*)d_in[11];
    const float* br      = (const float*)d_in[12];
    const float* att     = (const float*)d_in[13];
    const float* bias    = (const float*)d_in[14];
    const float* Wpi     = (const float*)d_in[15];
    const float* bpi     = (const float*)d_in[16];
    const float* Wa      = (const float*)d_in[17];
    const float* ba      = (const float*)d_in[18];
    const float* Wb      = (const float*)d_in[19];
    const float* bb      = (const float*)d_in[20];
    float* out = (float*)d_out;

    const int smem_bytes = SMEM_FLOATS * 4;  // 94464 B
    cudaFuncSetAttribute(nam_mma_kernel,
                         cudaFuncAttributeMaxDynamicSharedMemorySize, smem_bytes);
    nam_mma_kernel<<<B_TOT / BT_, NTHREADS, smem_bytes>>>(
        x, centers, logw, W1, b1, g1, be1, W2, b2, g2, be2,
        Wr, br, att, bias, Wpi, bpi, Wa, ba, Wb, bb, out);
}

// round 3
// speedup vs baseline: 1.9233x; 1.0010x over previous
#include <cuda_runtime.h>
#include <cstdint>

#define B_TOT 16384
#define F_    64
#define BT_   64
#define NTHREADS 256

// SMEM float offsets
#define RBF_OFF 0            // 64 x 68   = 4352
#define A1_OFF  4352         // 64 x 132  = 8448
#define WS_OFF  12800        // 64 x 136  = 8704
#define PB_OFF  21504        // 7 x 128   = 896
#define WFS_OFF 22400        // 64
#define LN_OFF  22464        // 2*64*2 = 256 (reused as head buf 2*64*9 = 1152)
#define SMEM_FLOATS (22464 + 1152)

#define SA_RBF 68
#define SA_A1  132
#define SW     136

__device__ __forceinline__ uint32_t f2tf32(float f) {
    uint32_t u;
    asm("cvt.rna.tf32.f32 %0, %1;" : "=r"(u) : "f"(f));
    return u;
}
__device__ __forceinline__ void mma8(float (&d)[4],
                                     uint32_t a0, uint32_t a1, uint32_t a2, uint32_t a3,
                                     uint32_t b0, uint32_t b1) {
    asm("mma.sync.aligned.m16n8k8.row.col.f32.tf32.tf32.f32 "
        "{%0,%1,%2,%3},{%4,%5,%6,%7},{%8,%9},{%0,%1,%2,%3};"
        : "+f"(d[0]), "+f"(d[1]), "+f"(d[2]), "+f"(d[3])
        : "r"(a0), "r"(a1), "r"(a2), "r"(a3), "r"(b0), "r"(b1));
}
__device__ __forceinline__ float clampf(float v, float lo, float hi) {
    return fminf(fmaxf(v, lo), hi);
}
__device__ __forceinline__ float gelu_f(float x) {
    return 0.5f * x * (1.0f + erff(x * 0.7071067811865475f));
}
__device__ __forceinline__ float softplus_f(float x) {
    return (x > 15.0f) ? x : log1pf(expf(x));
}
__device__ __forceinline__ float quad_sum(float v) {
    v += __shfl_xor_sync(0xffffffffu, v, 1);
    v += __shfl_xor_sync(0xffffffffu, v, 2);
    return v;
}

// KSTEPS k-chunks of 8. A: padded row-major [rows][strideA], tf32 bits.
// ws: padded [64][SW] tf32 bits. acc[j] covers n-tile j (cols nbase + j*8).
template<int KSTEPS>
__device__ __forceinline__ void gemm_steps(float (&acc)[8][4],
                                           const float* __restrict__ A, int sA, int rA0,
                                           const float* __restrict__ ws, int nbg, int t,
                                           int kA0)
{
#pragma unroll
    for (int ks = 0; ks < KSTEPS; ++ks) {
        const int k = ks * 8;
        const float* ar0 = A + rA0 * sA + kA0 + k + t;
        const float* ar1 = ar0 + 8 * sA;
        uint32_t a0 = __float_as_uint(ar0[0]);
        uint32_t a2 = __float_as_uint(ar0[4]);
        uint32_t a1 = __float_as_uint(ar1[0]);
        uint32_t a3 = __float_as_uint(ar1[4]);
        const float* wp0 = ws + (k + t) * SW + nbg;
        const float* wp1 = wp0 + 4 * SW;
#pragma unroll
        for (int j = 0; j < 8; ++j) {
            uint32_t b0 = __float_as_uint(wp0[j * 8]);
            uint32_t b1 = __float_as_uint(wp1[j * 8]);
            mma8(acc[j], a0, a1, a2, a3, b0, b1);
        }
    }
}

// stage 64x128 weight block (row-major, 2048 float4) into ws with tf32 cvt
__device__ __forceinline__ void stage_w(float* __restrict__ ws,
                                        const float4* __restrict__ g, int tid)
{
#pragma unroll
    for (int kk = 0; kk < 8; ++kk) {
        int idx = tid + kk * NTHREADS;
        int k = idx >> 5, n4 = idx & 31;
        float4 v = g[idx];
        uint4 u = make_uint4(f2tf32(v.x), f2tf32(v.y), f2tf32(v.z), f2tf32(v.w));
        *(uint4*)&ws[k * SW + n4 * 4] = u;
    }
}

__global__ void __launch_bounds__(NTHREADS, 2)
nam_mma_kernel(const float* __restrict__ x,
               const float* __restrict__ centers,
               const float* __restrict__ logw,
               const float* __restrict__ W1,  const float* __restrict__ b1,
               const float* __restrict__ g1,  const float* __restrict__ be1,
               const float* __restrict__ W2,  const float* __restrict__ b2,
               const float* __restrict__ g2,  const float* __restrict__ be2,
               const float* __restrict__ Wr,  const float* __restrict__ br,
               const float* __restrict__ att, const float* __restrict__ bias,
               const float* __restrict__ Wpi, const float* __restrict__ bpi,
               const float* __restrict__ Wa,  const float* __restrict__ ba,
               const float* __restrict__ Wb,  const float* __restrict__ bb,
               float* __restrict__ out)
{
    extern __shared__ float sm[];
    float* rbf = sm + RBF_OFF;
    float* a1s = sm + A1_OFF;
    float* ws  = sm + WS_OFF;
    float* pb  = sm + PB_OFF;
    float* wfs = sm + WFS_OFF;
    float* lnb = sm + LN_OFF;
    float* hb  = sm + LN_OFF;   // reused after feature loop

    const int tid  = threadIdx.x;
    const int wid  = tid >> 5;
    const int lane = tid & 31;
    const int g    = lane >> 2;    // 0..7
    const int t    = lane & 3;     // 0..3
    const int wr   = wid >> 1;     // row group 0..3
    const int wc   = wid & 1;      // col group 0..1
    const int rA0  = wr * 16 + g;  // thread row 0 (row 1 = +8)
    const int nbg  = wc * 64 + g;  // B-fragment col base
    const int b0blk = blockIdx.x * BT_;

    if (tid == 0) {
        float mx = -3.4e38f;
        for (int i = 0; i < F_; ++i) mx = fmaxf(mx, att[i]);
        float s = 0.0f;
        for (int i = 0; i < F_; ++i) { float e = expf(att[i] - mx); wfs[i] = e; s += e; }
        float inv = 1.0f / s;
        for (int i = 0; i < F_; ++i) wfs[i] *= inv;
    }

    float agg[2][16];
#pragma unroll
    for (int r = 0; r < 2; ++r)
#pragma unroll
        for (int j = 0; j < 16; ++j) agg[r][j] = 0.0f;

    for (int f = 0; f < F_; ++f) {
        __syncthreads();  // S0: rbf/ws/pb free

        // ---- RBF expansion (tf32-rounded into padded smem) ----
#pragma unroll
        for (int kk = 0; kk < 16; ++kk) {
            int idx = tid + kk * NTHREADS;
            int r = idx >> 6, n = idx & 63;
            float xv = clampf(x[(b0blk + r) * F_ + f], -10.0f, 10.0f);
            float c  = centers[f * 64 + n];
            float lw = clampf(logw[f * 64 + n], -5.0f, 5.0f);
            float wd = __expf(lw) + 0.1f;
            float d  = clampf(__fdividef(xv - c, wd), -10.0f, 10.0f);
            rbf[r * SA_RBF + n] = __uint_as_float(f2tf32(__expf(-0.5f * d * d)));
        }
        // ---- stage W1 + per-feature params ----
        stage_w(ws, (const float4*)(W1 + (size_t)f * 8192), tid);
        if (tid < 128) {
            pb[tid]       = b1 [f * 128 + tid];
            pb[128 + tid] = g1 [f * 128 + tid];
            pb[256 + tid] = be1[f * 128 + tid];
            pb[384 + tid] = b2 [f * 128 + tid];
        } else {
            int s = tid - 128;
            pb[512 + s] = g2 [f * 128 + s];
            pb[640 + s] = be2[f * 128 + s];
            pb[768 + s] = br [f * 128 + s];
        }
        __syncthreads();  // S1

        // ---- GEMM1: rbf[64x64] @ W1[64x128] ----
        float acc[8][4];
#pragma unroll
        for (int j = 0; j < 8; ++j) { acc[j][0] = acc[j][1] = acc[j][2] = acc[j][3] = 0.f; }
        gemm_steps<8>(acc, rbf, SA_RBF, rA0, ws, nbg, t, 0);

        // partial LN stats (with +b1)
        {
            float s0 = 0.f, q0 = 0.f, s1 = 0.f, q1 = 0.f;
#pragma unroll
            for (int j = 0; j < 8; ++j) {
                int col = wc * 64 + j * 8 + t * 2;
                float2 bv = *(const float2*)&pb[col];
                float v0 = acc[j][0] + bv.x, v1 = acc[j][1] + bv.y;
                float v2 = acc[j][2] + bv.x, v3 = acc[j][3] + bv.y;
                s0 += v0 + v1; q0 += v0 * v0 + v1 * v1;
                s1 += v2 + v3; q1 += v2 * v2 + v3 * v3;
            }
            s0 = quad_sum(s0); q0 = quad_sum(q0);
            s1 = quad_sum(s1); q1 = quad_sum(q1);
            if (t == 0) {
                *(float2*)&lnb[(wc * 64 + rA0) * 2]     = make_float2(s0, q0);
                *(float2*)&lnb[(wc * 64 + rA0 + 8) * 2] = make_float2(s1, q1);
            }
        }
        __syncthreads();  // S2

        // finalize epilogue 1 -> a1s ; stage W2 half0
        {
            float2 pA0 = *(const float2*)&lnb[rA0 * 2];
            float2 pB0 = *(const float2*)&lnb[(64 + rA0) * 2];
            float2 pA1 = *(const float2*)&lnb[(rA0 + 8) * 2];
            float2 pB1 = *(const float2*)&lnb[(64 + rA0 + 8) * 2];
            float mu0 = (pA0.x + pB0.x) * (1.f / 128.f);
            float va0 = (pA0.y + pB0.y) * (1.f / 128.f) - mu0 * mu0;
            float rs0 = rsqrtf(va0 + 1e-5f);
            float mu1 = (pA1.x + pB1.x) * (1.f / 128.f);
            float va1 = (pA1.y + pB1.y) * (1.f / 128.f) - mu1 * mu1;
            float rs1 = rsqrtf(va1 + 1e-5f);
#pragma unroll
            for (int j = 0; j < 8; ++j) {
                int col = wc * 64 + j * 8 + t * 2;
                float2 bv = *(const float2*)&pb[col];
                float2 gv = *(const float2*)&pb[128 + col];
                float2 ev = *(const float2*)&pb[256 + col];
                float v0 = gelu_f((acc[j][0] + bv.x - mu0) * rs0 * gv.x + ev.x);
                float v1 = gelu_f((acc[j][1] + bv.y - mu0) * rs0 * gv.y + ev.y);
                float v2 = gelu_f((acc[j][2] + bv.x - mu1) * rs1 * gv.x + ev.x);
                float v3 = gelu_f((acc[j][3] + bv.y - mu1) * rs1 * gv.y + ev.y);
                *(float2*)&a1s[rA0 * SA_A1 + col] =
                    make_float2(__uint_as_float(f2tf32(v0)), __uint_as_float(f2tf32(v1)));
                *(float2*)&a1s[(rA0 + 8) * SA_A1 + col] =
                    make_float2(__uint_as_float(f2tf32(v2)), __uint_as_float(f2tf32(v3)));
            }
        }
        stage_w(ws, (const float4*)(W2 + (size_t)f * 16384), tid);
        __syncthreads();  // S3

        float acc2[8][4];
#pragma unroll
        for (int j = 0; j < 8; ++j) { acc2[j][0] = acc2[j][1] = acc2[j][2] = acc2[j][3] = 0.f; }
        gemm_steps<8>(acc2, a1s, SA_A1, rA0, ws, nbg, t, 0);
        __syncthreads();  // S4
        stage_w(ws, (const float4*)(W2 + (size_t)f * 16384) + 2048, tid);
        __syncthreads();  // S5
        gemm_steps<8>(acc2, a1s, SA_A1, rA0, ws, nbg, t, 64);

        // partial LN stats (with +b2)
        {
            float s0 = 0.f, q0 = 0.f, s1 = 0.f, q1 = 0.f;
#pragma unroll
            for (int j = 0; j < 8; ++j) {
                int col = wc * 64 + j * 8 + t * 2;
                float2 bv = *(const float2*)&pb[384 + col];
                float v0 = acc2[j][0] + bv.x, v1 = acc2[j][1] + bv.y;
                float v2 = acc2[j][2] + bv.x, v3 = acc2[j][3] + bv.y;
                s0 += v0 + v1; q0 += v0 * v0 + v1 * v1;
                s1 += v2 + v3; q1 += v2 * v2 + v3 * v3;
            }
            s0 = quad_sum(s0); q0 = quad_sum(q0);
            s1 = quad_sum(s1); q1 = quad_sum(q1);
            if (t == 0) {
                *(float2*)&lnb[(wc * 64 + rA0) * 2]     = make_float2(s0, q0);
                *(float2*)&lnb[(wc * 64 + rA0 + 8) * 2] = make_float2(s1, q1);
            }
        }
        __syncthreads();  // S6

        const float wf = wfs[f];
        {
            float2 pA0 = *(const float2*)&lnb[rA0 * 2];
            float2 pB0 = *(const float2*)&lnb[(64 + rA0) * 2];
            float2 pA1 = *(const float2*)&lnb[(rA0 + 8) * 2];
            float2 pB1 = *(const float2*)&lnb[(64 + rA0 + 8) * 2];
            float mu0 = (pA0.x + pB0.x) * (1.f / 128.f);
            float va0 = (pA0.y + pB0.y) * (1.f / 128.f) - mu0 * mu0;
            float rs0 = rsqrtf(va0 + 1e-5f);
            float mu1 = (pA1.x + pB1.x) * (1.f / 128.f);
            float va1 = (pA1.y + pB1.y) * (1.f / 128.f) - mu1 * mu1;
            float rs1 = rsqrtf(va1 + 1e-5f);
#pragma unroll
            for (int j = 0; j < 8; ++j) {
                int col = wc * 64 + j * 8 + t * 2;
                float2 bv = *(const float2*)&pb[384 + col];
                float2 gv = *(const float2*)&pb[512 + col];
                float2 ev = *(const float2*)&pb[640 + col];
                float v0 = gelu_f((acc2[j][0] + bv.x - mu0) * rs0 * gv.x + ev.x);
                float v1 = gelu_f((acc2[j][1] + bv.y - mu0) * rs0 * gv.y + ev.y);
                float v2 = gelu_f((acc2[j][2] + bv.x - mu1) * rs1 * gv.x + ev.x);
                float v3 = gelu_f((acc2[j][3] + bv.y - mu1) * rs1 * gv.y + ev.y);
                agg[0][j * 2]     += wf * v0;
                agg[0][j * 2 + 1] += wf * v1;
                agg[1][j * 2]     += wf * v2;
                agg[1][j * 2 + 1] += wf * v3;
            }
        }
        stage_w(ws, (const float4*)(Wr + (size_t)f * 8192), tid);
        __syncthreads();  // S7

        float accr[8][4];
#pragma unroll
        for (int j = 0; j < 8; ++j) { accr[j][0] = accr[j][1] = accr[j][2] = accr[j][3] = 0.f; }
        gemm_steps<8>(accr, rbf, SA_RBF, rA0, ws, nbg, t, 0);
        {
            const float c01 = 0.1f * wf;
#pragma unroll
            for (int j = 0; j < 8; ++j) {
                int col = wc * 64 + j * 8 + t * 2;
                float2 bv = *(const float2*)&pb[768 + col];
                agg[0][j * 2]     += c01 * (accr[j][0] + bv.x);
                agg[0][j * 2 + 1] += c01 * (accr[j][1] + bv.y);
                agg[1][j * 2]     += c01 * (accr[j][2] + bv.x);
                agg[1][j * 2 + 1] += c01 * (accr[j][3] + bv.y);
            }
        }
    }

    // ---- mixture-beta head ----
    float p[2][9];
#pragma unroll
    for (int r = 0; r < 2; ++r)
#pragma unroll
        for (int q = 0; q < 9; ++q) p[r][q] = 0.f;

#pragma unroll
    for (int j = 0; j < 8; ++j) {
#pragma unroll
        for (int cc = 0; cc < 2; ++cc) {
            int c = wc * 64 + j * 8 + t * 2 + cc;
            float bs = __ldg(&bias[c]);
            float av0 = agg[0][j * 2 + cc] + bs;
            float av1 = agg[1][j * 2 + cc] + bs;
#pragma unroll
            for (int q = 0; q < 3; ++q) {
                float wp = __ldg(&Wpi[c * 3 + q]);
                float wa = __ldg(&Wa [c * 3 + q]);
                float wb = __ldg(&Wb [c * 3 + q]);
                p[0][q]     += av0 * wp; p[1][q]     += av1 * wp;
                p[0][3 + q] += av0 * wa; p[1][3 + q] += av1 * wa;
                p[0][6 + q] += av0 * wb; p[1][6 + q] += av1 * wb;
            }
        }
    }
#pragma unroll
    for (int r = 0; r < 2; ++r)
#pragma unroll
        for (int q = 0; q < 9; ++q) p[r][q] = quad_sum(p[r][q]);

    if (t == 0) {
#pragma unroll
        for (int q = 0; q < 9; ++q) {
            hb[(wc * 64 + rA0) * 9 + q]     = p[0][q];
            hb[(wc * 64 + rA0 + 8) * 9 + q] = p[1][q];
        }
    }
    __syncthreads();

    if (wc == 0 && t == 0) {
#pragma unroll
        for (int rr = 0; rr < 2; ++rr) {
            int r = rA0 + rr * 8;
            float z[9];
#pragma unroll
            for (int q = 0; q < 9; ++q) z[q] = hb[r * 9 + q] + hb[(64 + r) * 9 + q];
            float p0 = z[0] + bpi[0], p1 = z[1] + bpi[1], p2 = z[2] + bpi[2];
            float m = fmaxf(p0, fmaxf(p1, p2));
            float e0 = expf(p0 - m), e1 = expf(p1 - m), e2 = expf(p2 - m);
            float al0 = clampf(softplus_f(z[3] + ba[0]) + 1.01f, 1.01f, 100.0f);
            float al1 = clampf(softplus_f(z[4] + ba[1]) + 1.01f, 1.01f, 100.0f);
            float al2 = clampf(softplus_f(z[5] + ba[2]) + 1.01f, 1.01f, 100.0f);
            float bt0 = clampf(softplus_f(z[6] + bb[0]) + 1.01f, 1.01f, 100.0f);
            float bt1 = clampf(softplus_f(z[7] + bb[1]) + 1.01f, 1.01f, 100.0f);
            float bt2 = clampf(softplus_f(z[8] + bb[2]) + 1.01f, 1.01f, 100.0f);
            float pred = e0 * al0 / (al0 + bt0)
                       + e1 * al1 / (al1 + bt1)
                       + e2 * al2 / (al2 + bt2);
            pred /= (e0 + e1 + e2);
            out[b0blk + r] = clampf(pred, 0.001f, 0.999f);
        }
    }
}

extern "C" void kernel_launch(void* const* d_in, const int* in_sizes, int n_in,
                              void* d_out, int out_size)
{
    const float* x       = (const float*)d_in[0];
    const float* centers = (const float*)d_in[1];
    const float* logw    = (const float*)d_in[2];
    const float* W1      = (const float*)d_in[3];
    const float* b1      = (const float*)d_in[4];
    const float* g1      = (const float*)d_in[5];
    const float* be1     = (const float*)d_in[6];
    const float* W2      = (const float*)d_in[7];
    const float* b2      = (const float*)d_in[8];
    const float* g2      = (const float*)d_in[9];
    const float* be2     = (const float*)d_in[10];
    const float* Wr      = (const float*)d_in[11];
    const float* br      = (const float*)d_in[12];
    const float* att     = (const float*)d_in[13];
    const float* bias    = (const float*)d_in[14];
    const float* Wpi     = (const float*)d_in[15];
    const float* bpi     = (const float*)d_in[16];
    const float* Wa      = (const float*)d_in[17];
    const float* ba      = (const float*)d_in[18];
    const float* Wb      = (const float*)d_in[19];
    const float* bb      = (const float*)d_in[20];
    float* out = (float*)d_out;

    const int smem_bytes = SMEM_FLOATS * 4;  // 94464 B
    cudaFuncSetAttribute(nam_mma_kernel,
                         cudaFuncAttributeMaxDynamicSharedMemorySize, smem_bytes);
    nam_mma_kernel<<<B_TOT / BT_, NTHREADS, smem_bytes>>>(
        x, centers, logw, W1, b1, g1, be1, W2, b2, g2, be2,
        Wr, br, att, bias, Wpi, bpi, Wa, ba, Wb, bb, out);
}

// round 5
// speedup vs baseline: 2.8135x; 1.4629x over previous
#include <cuda_runtime.h>
#include <cstdint>

#define NTH 512
#define SW 136
#define SA_RBF 68
#define SA_A1 132
// smem float offsets
#define RBFO 0
#define A1O  8704
#define BB0O 25600
#define BB1O 34304
#define PBO  43008
#define WFSO 43904
#define LNBO 43968
#define HBO  44480
#define SMF  46784

__device__ __forceinline__ uint32_t s2u(const void* p){
  uint32_t a;
  asm("{.reg .u64 t; cvta.to.shared.u64 t,%1; cvt.u32.u64 %0,t;}":"=r"(a):"l"(p));
  return a;
}
__device__ __forceinline__ void cpa16(uint32_t dst, const void* src){
  asm volatile("cp.async.cg.shared.global [%0], [%1], 16;"::"r"(dst),"l"(src):"memory");
}
#define CPCOMMIT() asm volatile("cp.async.commit_group;":::"memory")
#define CPWAIT1()  asm volatile("cp.async.wait_group 1;":::"memory")

__device__ __forceinline__ void mma8(float (&d)[4],
                                     uint32_t a0, uint32_t a1, uint32_t a2, uint32_t a3,
                                     uint32_t b0, uint32_t b1){
  asm("mma.sync.aligned.m16n8k8.row.col.f32.tf32.tf32.f32 "
      "{%0,%1,%2,%3},{%4,%5,%6,%7},{%8,%9},{%0,%1,%2,%3};"
      : "+f"(d[0]), "+f"(d[1]), "+f"(d[2]), "+f"(d[3])
      : "r"(a0), "r"(a1), "r"(a2), "r"(a3), "r"(b0), "r"(b1));
}
__device__ __forceinline__ float clampf(float v,float lo,float hi){return fminf(fmaxf(v,lo),hi);}
__device__ __forceinline__ float gelu_f(float x){
  float u = x*(0.7978845608f + 0.035677408f*x*x);
  float t; asm("tanh.approx.f32 %0, %1;":"=f"(t):"f"(u));
  return 0.5f*x*(1.0f+t);
}
__device__ __forceinline__ float softplus_f(float x){return (x>15.0f)?x:log1pf(expf(x));}
__device__ __forceinline__ float quad_sum(float v){
  v += __shfl_xor_sync(0xffffffffu, v, 1);
  v += __shfl_xor_sync(0xffffffffu, v, 2);
  return v;
}

template<int KSTEPS>
__device__ __forceinline__ void gemm_steps(float (&acc)[8][4],
                                           const float* __restrict__ A, int sA, int rA0,
                                           const float* __restrict__ ws, int nbg, int t,
                                           int kA0)
{
#pragma unroll 4
  for(int ks=0; ks<KSTEPS; ++ks){
    const int k = ks*8;
    const float* ar0 = A + rA0*sA + kA0 + k + t;
    const float* ar1 = ar0 + 8*sA;
    uint32_t a0 = __float_as_uint(ar0[0]);
    uint32_t a2 = __float_as_uint(ar0[4]);
    uint32_t a1 = __float_as_uint(ar1[0]);
    uint32_t a3 = __float_as_uint(ar1[4]);
    const float* wp0 = ws + (k+t)*SW + nbg;
    const float* wp1 = wp0 + 4*SW;
#pragma unroll
    for(int j=0;j<8;++j){
      uint32_t b0 = __float_as_uint(wp0[j*8]);
      uint32_t b1 = __float_as_uint(wp1[j*8]);
      mma8(acc[j], a0, a1, a2, a3, b0, b1);
    }
  }
}

// async-stage a 64k x 128n weight block (row-major gmem) into [k][SW] smem tile
__device__ __forceinline__ void stage64(uint32_t bufu, const float* __restrict__ W, int tid){
  int n4 = (tid & 31) << 2;
  int k0 = tid >> 5;
#pragma unroll
  for(int i=0;i<4;++i){
    int k = k0 + i*16;
    cpa16(bufu + (uint32_t)(k*SW + n4)*4u, W + k*128 + n4);
  }
}

__global__ void __launch_bounds__(NTH, 1)
nam_mma2_kernel(const float* __restrict__ x,const float* __restrict__ centers,
                const float* __restrict__ logw,
                const float* __restrict__ W1,const float* __restrict__ b1,
                const float* __restrict__ g1,const float* __restrict__ be1,
                const float* __restrict__ W2,const float* __restrict__ b2,
                const float* __restrict__ g2,const float* __restrict__ be2,
                const float* __restrict__ Wr,const float* __restrict__ br,
                const float* __restrict__ att,const float* __restrict__ bias,
                const float* __restrict__ Wpi,const float* __restrict__ bpi,
                const float* __restrict__ Wa,const float* __restrict__ ba,
                const float* __restrict__ Wb,const float* __restrict__ bb,
                float* __restrict__ out)
{
  extern __shared__ float sm[];
  float* rbf = sm + RBFO;
  float* a1s = sm + A1O;
  float* bb0 = sm + BB0O;
  float* bb1 = sm + BB1O;
  float* pbf = sm + PBO;
  float* wfs = sm + WFSO;
  float2* lnb = (float2*)(sm + LNBO);
  float* hb  = sm + HBO;
  const uint32_t bb0u = s2u(bb0), bb1u = s2u(bb1);

  const int tid = threadIdx.x;
  const int w = tid >> 5, lane = tid & 31;
  const int g = lane >> 2, t = lane & 3;
  const int wr = w >> 1, wc = w & 1;
  const int rA0 = wr*16 + g;        // rows rA0, rA0+8 (0..127)
  const int nbg = wc*64 + g;
  const int b0 = blockIdx.x * 128;

  if(tid == 0){
    float mx = -3.4e38f;
    for(int i=0;i<64;++i) mx = fmaxf(mx, att[i]);
    float s = 0.f;
    for(int i=0;i<64;++i){ float e = expf(att[i]-mx); wfs[i] = e; s += e; }
    float inv = 1.f/s;
    for(int i=0;i<64;++i) wfs[i] *= inv;
  }

  // prologue: prefetch W1(f0) -> bb0, W2a(f0) -> bb1
  stage64(bb0u, W1, tid); CPCOMMIT();
  stage64(bb1u, W2, tid); CPCOMMIT();

  float agg[2][16];
#pragma unroll
  for(int r2=0;r2<2;++r2)
#pragma unroll
    for(int j=0;j<16;++j) agg[r2][j] = 0.f;

  for(int f=0; f<64; ++f){
    const int fn = (f+1) & 63;
    __syncthreads();  // S0: prev iteration fully done (pb/rbf/lnb free)

    // ---- RBF -> rbf (raw f32; HMMA truncates to tf32) ----
#pragma unroll
    for(int it=0;it<4;++it){
      int gi = it*NTH + tid;
      int row = gi >> 4, n4 = (gi & 15) << 2;
      float xv = clampf(x[(b0+row)*64 + f], -10.f, 10.f);
      float4 ce = *(const float4*)&centers[f*64 + n4];
      float4 lw = *(const float4*)&logw[f*64 + n4];
      float4 o;
      { float wd=__expf(clampf(lw.x,-5.f,5.f))+0.1f; float d=clampf(__fdividef(xv-ce.x,wd),-10.f,10.f); o.x=__expf(-0.5f*d*d); }
      { float wd=__expf(clampf(lw.y,-5.f,5.f))+0.1f; float d=clampf(__fdividef(xv-ce.y,wd),-10.f,10.f); o.y=__expf(-0.5f*d*d); }
      { float wd=__expf(clampf(lw.z,-5.f,5.f))+0.1f; float d=clampf(__fdividef(xv-ce.z,wd),-10.f,10.f); o.z=__expf(-0.5f*d*d); }
      { float wd=__expf(clampf(lw.w,-5.f,5.f))+0.1f; float d=clampf(__fdividef(xv-ce.w,wd),-10.f,10.f); o.w=__expf(-0.5f*d*d); }
      *(float4*)&rbf[row*SA_RBF + n4] = o;
    }
    // ---- per-feature params -> pb ----
    for(int i=tid; i<896; i+=NTH){
      int seg = i >> 7, c = i & 127;
      const float* sp = (seg==0)?b1:(seg==1)?g1:(seg==2)?be1:(seg==3)?b2:(seg==4)?g2:(seg==5)?be2:br;
      pbf[i] = sp[f*128 + c];
    }
    CPWAIT1(); __syncthreads();   // S1: bb0 = W1 ready; rbf/pb visible

    // ---- GEMM1: rbf @ W1 ----
    float acc[8][4];
#pragma unroll
    for(int j=0;j<8;++j){ acc[j][0]=acc[j][1]=acc[j][2]=acc[j][3]=0.f; }
    gemm_steps<8>(acc, rbf, SA_RBF, rA0, bb0, nbg, t, 0);
    __syncthreads();              // S2: all warps done reading bb0
    stage64(bb0u, W2 + (size_t)f*16384 + 64*128, tid); CPCOMMIT();  // W2b -> bb0

    // LN1 stats (+b1)
    {
      float s0=0.f,q0=0.f,s1=0.f,q1=0.f;
#pragma unroll
      for(int j=0;j<8;++j){
        int col = wc*64 + j*8 + t*2;
        float2 bv = *(const float2*)&pbf[col];
        float v0=acc[j][0]+bv.x, v1=acc[j][1]+bv.y;
        float v2=acc[j][2]+bv.x, v3=acc[j][3]+bv.y;
        s0+=v0+v1; q0+=v0*v0+v1*v1;
        s1+=v2+v3; q1+=v2*v2+v3*v3;
      }
      s0=quad_sum(s0); q0=quad_sum(q0); s1=quad_sum(s1); q1=quad_sum(q1);
      if(t==0){
        lnb[rA0*2 + wc]     = make_float2(s0,q0);
        lnb[(rA0+8)*2 + wc] = make_float2(s1,q1);
      }
    }
    CPWAIT1(); __syncthreads();   // S3: bb1 = W2a ready; lnb visible

    // epilogue 1 -> a1s
    {
      float2 pA0 = lnb[rA0*2 + wc],     pB0 = lnb[rA0*2 + (wc^1)];
      float2 pA1 = lnb[(rA0+8)*2 + wc], pB1 = lnb[(rA0+8)*2 + (wc^1)];
      float mu0=(pA0.x+pB0.x)*(1.f/128.f);
      float rs0=rsqrtf((pA0.y+pB0.y)*(1.f/128.f)-mu0*mu0+1e-5f);
      float mu1=(pA1.x+pB1.x)*(1.f/128.f);
      float rs1=rsqrtf((pA1.y+pB1.y)*(1.f/128.f)-mu1*mu1+1e-5f);
#pragma unroll
      for(int j=0;j<8;++j){
        int col = wc*64 + j*8 + t*2;
        float2 bv = *(const float2*)&pbf[col];
        float2 gv = *(const float2*)&pbf[128+col];
        float2 ev = *(const float2*)&pbf[256+col];
        float v0 = gelu_f((acc[j][0]+bv.x-mu0)*rs0*gv.x+ev.x);
        float v1 = gelu_f((acc[j][1]+bv.y-mu0)*rs0*gv.y+ev.y);
        float v2 = gelu_f((acc[j][2]+bv.x-mu1)*rs1*gv.x+ev.x);
        float v3 = gelu_f((acc[j][3]+bv.y-mu1)*rs1*gv.y+ev.y);
        *(float2*)&a1s[rA0*SA_A1 + col]     = make_float2(v0,v1);
        *(float2*)&a1s[(rA0+8)*SA_A1 + col] = make_float2(v2,v3);
      }
    }
    __syncthreads();              // S4: a1 visible

    float acc2[8][4];
#pragma unroll
    for(int j=0;j<8;++j){ acc2[j][0]=acc2[j][1]=acc2[j][2]=acc2[j][3]=0.f; }
    gemm_steps<8>(acc2, a1s, SA_A1, rA0, bb1, nbg, t, 0);   // GEMM2a (W2a in bb1)
    __syncthreads();              // S5: bb1 free
    stage64(bb1u, Wr + (size_t)f*8192, tid); CPCOMMIT();    // Wr -> bb1
    CPWAIT1(); __syncthreads();   // S6: bb0 = W2b ready
    gemm_steps<8>(acc2, a1s, SA_A1, rA0, bb0, nbg, t, 64);  // GEMM2b
    __syncthreads();              // S7: bb0 free
    stage64(bb0u, W1 + (size_t)fn*8192, tid); CPCOMMIT();   // W1(next) -> bb0

    // LN2 stats (+b2)
    {
      float s0=0.f,q0=0.f,s1=0.f,q1=0.f;
#pragma unroll
      for(int j=0;j<8;++j){
        int col = wc*64 + j*8 + t*2;
        float2 bv = *(const float2*)&pbf[384+col];
        float v0=acc2[j][0]+bv.x, v1=acc2[j][1]+bv.y;
        float v2=acc2[j][2]+bv.x, v3=acc2[j][3]+bv.y;
        s0+=v0+v1; q0+=v0*v0+v1*v1;
        s1+=v2+v3; q1+=v2*v2+v3*v3;
      }
      s0=quad_sum(s0); q0=quad_sum(q0); s1=quad_sum(s1); q1=quad_sum(q1);
      if(t==0){
        lnb[rA0*2 + wc]     = make_float2(s0,q0);
        lnb[(rA0+8)*2 + wc] = make_float2(s1,q1);
      }
    }
    __syncthreads();              // S8: lnb visible

    const float wf = wfs[f];
    {
      float2 pA0 = lnb[rA0*2 + wc],     pB0 = lnb[rA0*2 + (wc^1)];
      float2 pA1 = lnb[(rA0+8)*2 + wc], pB1 = lnb[(rA0+8)*2 + (wc^1)];
      float mu0=(pA0.x+pB0.x)*(1.f/128.f);
      float rs0=rsqrtf((pA0.y+pB0.y)*(1.f/128.f)-mu0*mu0+1e-5f);
      float mu1=(pA1.x+pB1.x)*(1.f/128.f);
      float rs1=rsqrtf((pA1.y+pB1.y)*(1.f/128.f)-mu1*mu1+1e-5f);
#pragma unroll
      for(int j=0;j<8;++j){
        int col = wc*64 + j*8 + t*2;
        float2 bv = *(const float2*)&pbf[384+col];
        float2 gv = *(const float2*)&pbf[512+col];
        float2 ev = *(const float2*)&pbf[640+col];
        agg[0][j*2]   += wf*gelu_f((acc2[j][0]+bv.x-mu0)*rs0*gv.x+ev.x);
        agg[0][j*2+1] += wf*gelu_f((acc2[j][1]+bv.y-mu0)*rs0*gv.y+ev.y);
        agg[1][j*2]   += wf*gelu_f((acc2[j][2]+bv.x-mu1)*rs1*gv.x+ev.x);
        agg[1][j*2+1] += wf*gelu_f((acc2[j][3]+bv.y-mu1)*rs1*gv.y+ev.y);
      }
    }
    CPWAIT1(); __syncthreads();   // S9: bb1 = Wr ready
    float accr[8][4];
#pragma unroll
    for(int j=0;j<8;++j){ accr[j][0]=accr[j][1]=accr[j][2]=accr[j][3]=0.f; }
    gemm_steps<8>(accr, rbf, SA_RBF, rA0, bb1, nbg, t, 0);  // GEMMr
    __syncthreads();              // S10: bb1 free
    stage64(bb1u, W2 + (size_t)fn*16384, tid); CPCOMMIT();  // W2a(next) -> bb1
    {
      const float cr = 0.1f*wf;
#pragma unroll
      for(int j=0;j<8;++j){
        int col = wc*64 + j*8 + t*2;
        float2 bv = *(const float2*)&pbf[768+col];
        agg[0][j*2]   += cr*(accr[j][0]+bv.x);
        agg[0][j*2+1] += cr*(accr[j][1]+bv.y);
        agg[1][j*2]   += cr*(accr[j][2]+bv.x);
        agg[1][j*2+1] += cr*(accr[j][3]+bv.y);
      }
    }
  }

  // ---- mixture-beta head ----
  float p[2][9];
#pragma unroll
  for(int r2=0;r2<2;++r2)
#pragma unroll
    for(int q=0;q<9;++q) p[r2][q]=0.f;
#pragma unroll
  for(int j=0;j<8;++j){
#pragma unroll
    for(int cc=0;cc<2;++cc){
      int c = wc*64 + j*8 + t*2 + cc;
      float bs = __ldg(&bias[c]);
      float av0 = agg[0][j*2+cc] + bs;
      float av1 = agg[1][j*2+cc] + bs;
#pragma unroll
      for(int q=0;q<3;++q){
        float wp=__ldg(&Wpi[c*3+q]);
        float wa=__ldg(&Wa[c*3+q]);
        float wb=__ldg(&Wb[c*3+q]);
        p[0][q]+=av0*wp;   p[1][q]+=av1*wp;
        p[0][3+q]+=av0*wa; p[1][3+q]+=av1*wa;
        p[0][6+q]+=av0*wb; p[1][6+q]+=av1*wb;
      }
    }
  }
#pragma unroll
  for(int r2=0;r2<2;++r2)
#pragma unroll
    for(int q=0;q<9;++q) p[r2][q]=quad_sum(p[r2][q]);

  __syncthreads();  // hb region free (reuses smem after loop)
  if(t==0){
#pragma unroll
    for(int q=0;q<9;++q){
      hb[(wc*128 + rA0)*9 + q]     = p[0][q];
      hb[(wc*128 + rA0 + 8)*9 + q] = p[1][q];
    }
  }
  __syncthreads();

  if(wc==0 && t==0){
#pragma unroll
    for(int rr=0;rr<2;++rr){
      int r = rA0 + rr*8;
      float z[9];
#pragma unroll
      for(int q=0;q<9;++q) z[q] = hb[r*9+q] + hb[(128+r)*9+q];
      float p0=z[0]+bpi[0], p1=z[1]+bpi[1], p2=z[2]+bpi[2];
      float m=fmaxf(p0,fmaxf(p1,p2));
      float e0=expf(p0-m), e1=expf(p1-m), e2=expf(p2-m);
      float al0=clampf(softplus_f(z[3]+ba[0])+1.01f,1.01f,100.f);
      float al1=clampf(softplus_f(z[4]+ba[1])+1.01f,1.01f,100.f);
      float al2=clampf(softplus_f(z[5]+ba[2])+1.01f,1.01f,100.f);
      float bt0=clampf(softplus_f(z[6]+bb[0])+1.01f,1.01f,100.f);
      float bt1=clampf(softplus_f(z[7]+bb[1])+1.01f,1.01f,100.f);
      float bt2=clampf(softplus_f(z[8]+bb[2])+1.01f,1.01f,100.f);
      float pred=e0*al0/(al0+bt0)+e1*al1/(al1+bt1)+e2*al2/(al2+bt2);
      pred/=(e0+e1+e2);
      out[b0+r]=clampf(pred,0.001f,0.999f);
    }
  }
}

extern "C" void kernel_launch(void* const* d_in,const int* in_sizes,int n_in,
                              void* d_out,int out_size)
{
  const float* x=(const float*)d_in[0];
  const float* centers=(const float*)d_in[1];
  const float* logw=(const float*)d_in[2];
  const float* W1=(const float*)d_in[3];
  const float* b1=(const float*)d_in[4];
  const float* g1=(const float*)d_in[5];
  const float* be1=(const float*)d_in[6];
  const float* W2=(const float*)d_in[7];
  const float* b2=(const float*)d_in[8];
  const float* g2=(const float*)d_in[9];
  const float* be2=(const float*)d_in[10];
  const float* Wr=(const float*)d_in[11];
  const float* br=(const float*)d_in[12];
  const float* att=(const float*)d_in[13];
  const float* bias=(const float*)d_in[14];
  const float* Wpi=(const float*)d_in[15];
  const float* bpi=(const float*)d_in[16];
  const float* Wa=(const float*)d_in[17];
  const float* ba=(const float*)d_in[18];
  const float* Wb=(const float*)d_in[19];
  const float* bb=(const float*)d_in[20];
  float* out=(float*)d_out;

  const int smem_bytes = SMF*4;   // 187136 B
  cudaFuncSetAttribute(nam_mma2_kernel,cudaFuncAttributeMaxDynamicSharedMemorySize,smem_bytes);
  nam_mma2_kernel<<<128,NTH,smem_bytes>>>(x,centers,logw,W1,b1,g1,be1,W2,b2,g2,be2,
                                          Wr,br,att,bias,Wpi,bpi,Wa,ba,Wb,bb,out);
}